// round 2
// baseline (speedup 1.0000x reference)
#include <cuda_runtime.h>

#define N_USERS    50000
#define N_ENTITIES 100000
#define CHANNEL    64
#define N_FACTORS  4
#define N_RELM1    8
#define N_EDGES    1500000
#define NNZ        800000

// 64 channels = 16 float4 per row
#define EV4 (N_ENTITIES * 16)
#define UV4 (N_USERS * 16)

__device__ float4 g_ent_cur[EV4];
__device__ float4 g_ent_agg[EV4];
__device__ float4 g_usr_cur[UV4];
__device__ float4 g_usr_agg[UV4];
__device__ float  g_disen[N_FACTORS * CHANNEL];   // softmax(att) @ weight

// ---------------------------------------------------------------------------
// init: copy inputs into working buffers AND initialize the output accumulators
// ---------------------------------------------------------------------------
__global__ void k_init(const float4* __restrict__ ent, const float4* __restrict__ usr,
                       float4* __restrict__ out_ent, float4* __restrict__ out_usr) {
    int i = blockIdx.x * blockDim.x + threadIdx.x;
    if (i < EV4) {
        float4 v = ent[i];
        g_ent_cur[i] = v;
        out_ent[i]   = v;
    } else {
        int j = i - EV4;
        if (j < UV4) {
            float4 v = usr[j];
            g_usr_cur[j] = v;
            out_usr[j]   = v;
        }
    }
}

// ---------------------------------------------------------------------------
// zero the aggregation buffers (per hop)
// ---------------------------------------------------------------------------
__global__ void k_zero() {
    int i = blockIdx.x * blockDim.x + threadIdx.x;
    float4 z = make_float4(0.f, 0.f, 0.f, 0.f);
    if (i < EV4) g_ent_agg[i] = z;
    else {
        int j = i - EV4;
        if (j < UV4) g_usr_agg[j] = z;
    }
}

// ---------------------------------------------------------------------------
// small kernel: distance-correlation scalar + disen_weight = softmax(att) @ W
// ---------------------------------------------------------------------------
__device__ float dcor_pair(const float* t1, const float* t2) {
    const int ch = N_RELM1;
    float a[N_RELM1][N_RELM1], b[N_RELM1][N_RELM1];
    for (int i = 0; i < ch; i++)
        for (int j = 0; j < ch; j++) {
            float v1 = t1[i] * t1[i] - 2.f * t1[i] * t1[j] + t1[j] * t1[j];
            float v2 = t2[i] * t2[i] - 2.f * t2[i] * t2[j] + t2[j] * t2[j];
            a[i][j] = sqrtf(fmaxf(v1, 0.f) + 1e-8f);
            b[i][j] = sqrtf(fmaxf(v2, 0.f) + 1e-8f);
        }
    float arm[N_RELM1], acm[N_RELM1], brm[N_RELM1], bcm[N_RELM1];
    float am = 0.f, bm = 0.f;
    for (int i = 0; i < ch; i++) { arm[i] = acm[i] = brm[i] = bcm[i] = 0.f; }
    for (int i = 0; i < ch; i++)
        for (int j = 0; j < ch; j++) {
            arm[i] += a[i][j]; acm[j] += a[i][j]; am += a[i][j];
            brm[i] += b[i][j]; bcm[j] += b[i][j]; bm += b[i][j];
        }
    float inv = 1.f / (float)ch;
    for (int i = 0; i < ch; i++) { arm[i] *= inv; acm[i] *= inv; brm[i] *= inv; bcm[i] *= inv; }
    am *= inv * inv; bm *= inv * inv;
    float sAB = 0.f, sAA = 0.f, sBB = 0.f;
    for (int i = 0; i < ch; i++)
        for (int j = 0; j < ch; j++) {
            float A = a[i][j] - acm[j] - arm[i] + am;
            float B = b[i][j] - bcm[j] - brm[i] + bm;
            sAB += A * B; sAA += A * A; sBB += B * B;
        }
    float n2 = (float)(ch * ch);
    float dAB = sqrtf(fmaxf(sAB / n2, 0.f) + 1e-8f);
    float dAA = sqrtf(fmaxf(sAA / n2, 0.f) + 1e-8f);
    float dBB = sqrtf(fmaxf(sBB / n2, 0.f) + 1e-8f);
    return dAB / sqrtf(dAA * dBB + 1e-8f);
}

__global__ void k_small(const float* __restrict__ att, const float* __restrict__ w,
                        float* __restrict__ out_cor) {
    int t = threadIdx.x;  // 256 threads: t = f*64 + c
    // disen_weight = softmax(att, axis=-1) @ weight  -> (4, 64)
    if (t < N_FACTORS * CHANNEL) {
        int f = t >> 6, c = t & 63;
        float row[N_RELM1];
        float mx = -1e30f;
        for (int j = 0; j < N_RELM1; j++) { row[j] = att[f * N_RELM1 + j]; mx = fmaxf(mx, row[j]); }
        float s = 0.f;
        for (int j = 0; j < N_RELM1; j++) { row[j] = expf(row[j] - mx); s += row[j]; }
        float invs = 1.f / s;
        float acc = 0.f;
        for (int j = 0; j < N_RELM1; j++) acc += row[j] * invs * w[j * CHANNEL + c];
        g_disen[t] = acc;
    }
    if (t == 0) {
        float rows[N_FACTORS][N_RELM1];
        for (int f = 0; f < N_FACTORS; f++)
            for (int j = 0; j < N_RELM1; j++) rows[f][j] = att[f * N_RELM1 + j];
        float cor = 0.f;
        for (int i = 0; i < N_FACTORS; i++)
            for (int j = i + 1; j < N_FACTORS; j++)
                cor += dcor_pair(rows[i], rows[j]);
        *out_cor = cor;
    }
}

// ---------------------------------------------------------------------------
// edge aggregation: 16 threads per edge, one float4 per thread, vector RED
// ---------------------------------------------------------------------------
__global__ void k_edge(const int* __restrict__ head, const int* __restrict__ tail,
                       const int* __restrict__ etype, const float4* __restrict__ w4) {
    int idx = blockIdx.x * blockDim.x + threadIdx.x;
    int e = idx >> 4;
    int q = idx & 15;
    if (e >= N_EDGES) return;
    int h = head[e], t = tail[e], r = etype[e] - 1;
    float4 em = g_ent_cur[t * 16 + q];
    float4 rl = w4[r * 16 + q];
    float4 m = make_float4(em.x * rl.x, em.y * rl.y, em.z * rl.z, em.w * rl.w);
    atomicAdd(&g_ent_agg[h * 16 + q], m);   // RED.E.ADD.F32.V4 (sm_90+)
}

// ---------------------------------------------------------------------------
// user interaction aggregation
// ---------------------------------------------------------------------------
__global__ void k_user(const int* __restrict__ rows, const int* __restrict__ cols,
                       const float* __restrict__ vals) {
    int idx = blockIdx.x * blockDim.x + threadIdx.x;
    int i = idx >> 4;
    int q = idx & 15;
    if (i >= NNZ) return;
    int r = rows[i], c = cols[i];
    float v = vals[i];
    float4 em = g_ent_cur[c * 16 + q];
    float4 m = make_float4(v * em.x, v * em.y, v * em.z, v * em.w);
    atomicAdd(&g_usr_agg[r * 16 + q], m);
}

// ---------------------------------------------------------------------------
// entity normalize + accumulate into output. One warp per entity.
// NOTE: l2_normalize(agg / cnt) == l2_normalize(agg) -> degree count skipped.
// ---------------------------------------------------------------------------
__global__ void k_ent_norm(float2* __restrict__ out_ent) {
    int gid = blockIdx.x * blockDim.x + threadIdx.x;
    int ent = gid >> 5;
    int lane = threadIdx.x & 31;
    if (ent >= N_ENTITIES) return;
    const float2* agg = (const float2*)g_ent_agg;
    float2 v = agg[ent * 32 + lane];
    float ss = v.x * v.x + v.y * v.y;
    #pragma unroll
    for (int o = 16; o; o >>= 1) ss += __shfl_xor_sync(0xFFFFFFFFu, ss, o);
    float inv = 1.f / fmaxf(sqrtf(ss), 1e-12f);
    v.x *= inv; v.y *= inv;
    ((float2*)g_ent_cur)[ent * 32 + lane] = v;
    float2 o = out_ent[ent * 32 + lane];
    o.x += v.x; o.y += v.y;
    out_ent[ent * 32 + lane] = o;
}

// ---------------------------------------------------------------------------
// user update: score=softmax(u @ latent^T), mix=score@disen, new=agg*(1+mix),
// normalize, accumulate. One warp per user, 2 channels per lane.
// ---------------------------------------------------------------------------
__global__ void k_usr_norm(const float2* __restrict__ latent2, float2* __restrict__ out_usr) {
    int gid = blockIdx.x * blockDim.x + threadIdx.x;
    int u = gid >> 5;
    int lane = threadIdx.x & 31;
    if (u >= N_USERS) return;

    float2 uc = ((const float2*)g_usr_cur)[u * 32 + lane];

    float d[N_FACTORS];
    #pragma unroll
    for (int f = 0; f < N_FACTORS; f++) {
        float2 lf = latent2[f * 32 + lane];
        float p = uc.x * lf.x + uc.y * lf.y;
        #pragma unroll
        for (int o = 16; o; o >>= 1) p += __shfl_xor_sync(0xFFFFFFFFu, p, o);
        d[f] = p;
    }
    float mx = fmaxf(fmaxf(d[0], d[1]), fmaxf(d[2], d[3]));
    float s[N_FACTORS], sum = 0.f;
    #pragma unroll
    for (int f = 0; f < N_FACTORS; f++) { s[f] = expf(d[f] - mx); sum += s[f]; }
    float invs = 1.f / sum;

    const float2* dw = (const float2*)g_disen;
    float2 mix = make_float2(0.f, 0.f);
    #pragma unroll
    for (int f = 0; f < N_FACTORS; f++) {
        float sf = s[f] * invs;
        float2 w2 = dw[f * 32 + lane];
        mix.x += sf * w2.x;
        mix.y += sf * w2.y;
    }

    float2 agg = ((const float2*)g_usr_agg)[u * 32 + lane];
    float2 un = make_float2(agg.x * (mix.x + 1.f), agg.y * (mix.y + 1.f));

    float ss = un.x * un.x + un.y * un.y;
    #pragma unroll
    for (int o = 16; o; o >>= 1) ss += __shfl_xor_sync(0xFFFFFFFFu, ss, o);
    float inv = 1.f / fmaxf(sqrtf(ss), 1e-12f);
    un.x *= inv; un.y *= inv;

    ((float2*)g_usr_cur)[u * 32 + lane] = un;
    float2 o = out_usr[u * 32 + lane];
    o.x += un.x; o.y += un.y;
    out_usr[u * 32 + lane] = o;
}

// ---------------------------------------------------------------------------
extern "C" void kernel_launch(void* const* d_in, const int* in_sizes, int n_in,
                              void* d_out, int out_size) {
    const float* user_emb   = (const float*)d_in[0];
    const float* entity_emb = (const float*)d_in[1];
    const float* latent_emb = (const float*)d_in[2];
    const float* weight     = (const float*)d_in[3];
    const float* att        = (const float*)d_in[4];
    const float* ivals      = (const float*)d_in[5];
    const int*   head       = (const int*)d_in[6];
    const int*   tail       = (const int*)d_in[7];
    const int*   etype      = (const int*)d_in[8];
    const int*   irows      = (const int*)d_in[9];
    const int*   icols      = (const int*)d_in[10];

    float* out     = (float*)d_out;
    float* out_ent = out;
    float* out_usr = out + (size_t)N_ENTITIES * CHANNEL;
    float* out_cor = out + (size_t)(N_ENTITIES + N_USERS) * CHANNEL;

    const int TPB = 256;
    int init_blocks = (EV4 + UV4 + TPB - 1) / TPB;

    k_init<<<init_blocks, TPB>>>((const float4*)entity_emb, (const float4*)user_emb,
                                 (float4*)out_ent, (float4*)out_usr);
    k_small<<<1, 256>>>(att, weight, out_cor);

    for (int hop = 0; hop < 2; hop++) {
        k_zero<<<init_blocks, TPB>>>();
        k_edge<<<(N_EDGES * 16 + TPB - 1) / TPB, TPB>>>(head, tail, etype, (const float4*)weight);
        k_user<<<(NNZ * 16 + TPB - 1) / TPB, TPB>>>(irows, icols, ivals);
        k_ent_norm<<<(N_ENTITIES * 32 + TPB - 1) / TPB, TPB>>>((float2*)out_ent);
        k_usr_norm<<<(N_USERS * 32 + TPB - 1) / TPB, TPB>>>((const float2*)latent_emb,
                                                            (float2*)out_usr);
    }
}

// round 3
// speedup vs baseline: 1.4440x; 1.4440x over previous
#include <cuda_runtime.h>

#define N_USERS    50000
#define N_ENTITIES 100000
#define CHANNEL    64
#define N_FACTORS  4
#define N_RELM1    8
#define N_EDGES    1500000
#define NNZ        800000

#define NBINS   (N_ENTITIES + N_USERS)          // entity bins first, then user bins
#define NITEMS  (N_EDGES + NNZ)
#define CHUNK   1024
#define NBLK    ((NBINS + CHUNK - 1) / CHUNK)   // 147

#define EV4 (N_ENTITIES * 16)
#define UV4 (N_USERS * 16)

// ping-pong embedding buffers (float4-aligned)
__device__ float4 g_e0[EV4];
__device__ float4 g_e1[EV4];
__device__ float4 g_u0[UV4];
__device__ float4 g_u1[UV4];
__device__ float  g_disen[N_FACTORS * CHANNEL];

// CSR build
__device__ int   g_cnt[NBINS];
__device__ int   g_off[NBINS];
__device__ int   g_pos[NBINS];
__device__ int   g_bsum[NBLK];
__device__ int   g_bpre[NBLK];
__device__ int   g_icol[NITEMS];   // edges: tail | (rel<<20); user: col
__device__ float g_fval[NNZ];      // sorted interact vals (pos - N_EDGES)

// ---------------------------------------------------------------------------
__global__ void k_init(const float4* __restrict__ ent, const float4* __restrict__ usr,
                       float4* __restrict__ out_ent, float4* __restrict__ out_usr) {
    int i = blockIdx.x * blockDim.x + threadIdx.x;
    if (i < EV4) {
        float4 v = ent[i];
        g_e0[i] = v;
        out_ent[i] = v;
    } else {
        int j = i - EV4;
        if (j < UV4) {
            float4 v = usr[j];
            g_u0[j] = v;
            out_usr[j] = v;
        }
    }
}

// ---------------------------------------------------------------------------
__global__ void k_zero_cnt() {
    int i = blockIdx.x * blockDim.x + threadIdx.x;
    if (i < NBINS) g_cnt[i] = 0;
}

__global__ void k_hist(const int* __restrict__ head, const int* __restrict__ irows) {
    int i = blockIdx.x * blockDim.x + threadIdx.x;
    if (i < N_EDGES) {
        atomicAdd(&g_cnt[head[i]], 1);
    } else if (i < NITEMS) {
        atomicAdd(&g_cnt[N_ENTITIES + irows[i - N_EDGES]], 1);
    }
}

// block partial sums
__global__ void k_scan1() {
    __shared__ int s[CHUNK];
    int b = blockIdx.x, t = threadIdx.x;
    int i = b * CHUNK + t;
    s[t] = (i < NBINS) ? g_cnt[i] : 0;
    __syncthreads();
    for (int o = CHUNK >> 1; o; o >>= 1) {
        if (t < o) s[t] += s[t + o];
        __syncthreads();
    }
    if (t == 0) g_bsum[b] = s[0];
}

// scan the block sums (NBLK <= 256)
__global__ void k_scan2() {
    __shared__ int s[256];
    int t = threadIdx.x;
    int v = (t < NBLK) ? g_bsum[t] : 0;
    s[t] = v;
    __syncthreads();
    for (int o = 1; o < 256; o <<= 1) {
        int x = (t >= o) ? s[t - o] : 0;
        __syncthreads();
        s[t] += x;
        __syncthreads();
    }
    if (t < NBLK) g_bpre[t] = s[t] - v;   // exclusive
}

// per-chunk scan + base -> offsets and scatter cursors
__global__ void k_scan3() {
    __shared__ int s[CHUNK];
    int b = blockIdx.x, t = threadIdx.x;
    int i = b * CHUNK + t;
    int v = (i < NBINS) ? g_cnt[i] : 0;
    s[t] = v;
    __syncthreads();
    for (int o = 1; o < CHUNK; o <<= 1) {
        int x = (t >= o) ? s[t - o] : 0;
        __syncthreads();
        s[t] += x;
        __syncthreads();
    }
    if (i < NBINS) {
        int off = g_bpre[b] + s[t] - v;   // exclusive prefix
        g_off[i] = off;
        g_pos[i] = off;
    }
}

__global__ void k_scatter(const int* __restrict__ head, const int* __restrict__ tail,
                          const int* __restrict__ etype,
                          const int* __restrict__ irows, const int* __restrict__ icols,
                          const float* __restrict__ ivals) {
    int i = blockIdx.x * blockDim.x + threadIdx.x;
    if (i < N_EDGES) {
        int h = head[i];
        int pos = atomicAdd(&g_pos[h], 1);
        g_icol[pos] = tail[i] | ((etype[i] - 1) << 20);
    } else if (i < NITEMS) {
        int j = i - N_EDGES;
        int r = irows[j];
        int pos = atomicAdd(&g_pos[N_ENTITIES + r], 1);
        g_icol[pos] = icols[j];
        g_fval[pos - N_EDGES] = ivals[j];
    }
}

// ---------------------------------------------------------------------------
// distance-correlation + disen_weight = softmax(att) @ W
// ---------------------------------------------------------------------------
__device__ float dcor_pair(const float* t1, const float* t2) {
    const int ch = N_RELM1;
    float a[N_RELM1][N_RELM1], b[N_RELM1][N_RELM1];
    for (int i = 0; i < ch; i++)
        for (int j = 0; j < ch; j++) {
            float v1 = t1[i] * t1[i] - 2.f * t1[i] * t1[j] + t1[j] * t1[j];
            float v2 = t2[i] * t2[i] - 2.f * t2[i] * t2[j] + t2[j] * t2[j];
            a[i][j] = sqrtf(fmaxf(v1, 0.f) + 1e-8f);
            b[i][j] = sqrtf(fmaxf(v2, 0.f) + 1e-8f);
        }
    float arm[N_RELM1], acm[N_RELM1], brm[N_RELM1], bcm[N_RELM1];
    float am = 0.f, bm = 0.f;
    for (int i = 0; i < ch; i++) { arm[i] = acm[i] = brm[i] = bcm[i] = 0.f; }
    for (int i = 0; i < ch; i++)
        for (int j = 0; j < ch; j++) {
            arm[i] += a[i][j]; acm[j] += a[i][j]; am += a[i][j];
            brm[i] += b[i][j]; bcm[j] += b[i][j]; bm += b[i][j];
        }
    float inv = 1.f / (float)ch;
    for (int i = 0; i < ch; i++) { arm[i] *= inv; acm[i] *= inv; brm[i] *= inv; bcm[i] *= inv; }
    am *= inv * inv; bm *= inv * inv;
    float sAB = 0.f, sAA = 0.f, sBB = 0.f;
    for (int i = 0; i < ch; i++)
        for (int j = 0; j < ch; j++) {
            float A = a[i][j] - acm[j] - arm[i] + am;
            float B = b[i][j] - bcm[j] - brm[i] + bm;
            sAB += A * B; sAA += A * A; sBB += B * B;
        }
    float n2 = (float)(ch * ch);
    float dAB = sqrtf(fmaxf(sAB / n2, 0.f) + 1e-8f);
    float dAA = sqrtf(fmaxf(sAA / n2, 0.f) + 1e-8f);
    float dBB = sqrtf(fmaxf(sBB / n2, 0.f) + 1e-8f);
    return dAB / sqrtf(dAA * dBB + 1e-8f);
}

__global__ void k_small(const float* __restrict__ att, const float* __restrict__ w,
                        float* __restrict__ out_cor) {
    int t = threadIdx.x;
    if (t < N_FACTORS * CHANNEL) {
        int f = t >> 6, c = t & 63;
        float row[N_RELM1];
        float mx = -1e30f;
        for (int j = 0; j < N_RELM1; j++) { row[j] = att[f * N_RELM1 + j]; mx = fmaxf(mx, row[j]); }
        float s = 0.f;
        for (int j = 0; j < N_RELM1; j++) { row[j] = expf(row[j] - mx); s += row[j]; }
        float invs = 1.f / s;
        float acc = 0.f;
        for (int j = 0; j < N_RELM1; j++) acc += row[j] * invs * w[j * CHANNEL + c];
        g_disen[t] = acc;
    }
    if (t == 0) {
        float rows[N_FACTORS][N_RELM1];
        for (int f = 0; f < N_FACTORS; f++)
            for (int j = 0; j < N_RELM1; j++) rows[f][j] = att[f * N_RELM1 + j];
        float cor = 0.f;
        for (int i = 0; i < N_FACTORS; i++)
            for (int j = i + 1; j < N_FACTORS; j++)
                cor += dcor_pair(rows[i], rows[j]);
        *out_cor = cor;
    }
}

// ---------------------------------------------------------------------------
// fused hop: warp-per-destination CSR aggregation + normalize + output accum.
//   warps [0, N_ENTITIES)           -> entity rows
//   warps [N_ENTITIES, NBINS)       -> user rows
// l2_normalize(agg/cnt) == l2_normalize(agg) -> degree normalization dropped.
// ---------------------------------------------------------------------------
__global__ void k_hop(int hop, const float* __restrict__ weight,
                      const float2* __restrict__ latent2,
                      float2* __restrict__ out_ent, float2* __restrict__ out_usr) {
    __shared__ float2 s_w[N_RELM1 * 32];   // 8 relations x 64ch as float2 lanes

    int tid = threadIdx.x;
    for (int i = tid; i < N_RELM1 * 32; i += blockDim.x)
        s_w[i] = ((const float2*)weight)[i];
    __syncthreads();

    int gw   = (blockIdx.x * blockDim.x + tid) >> 5;
    int lane = tid & 31;
    if (gw >= NBINS) return;

    const float2* ecur = hop ? (const float2*)g_e1 : (const float2*)g_e0;
    float2*       enxt = hop ? (float2*)g_e0       : (float2*)g_e1;
    const float2* ucur = hop ? (const float2*)g_u1 : (const float2*)g_u0;
    float2*       unxt = hop ? (float2*)g_u0       : (float2*)g_u1;

    int start = g_off[gw];
    int n     = g_cnt[gw];

    if (gw < N_ENTITIES) {
        // ---- entity aggregation: sum_e ecur[tail] * weight[rel] ----
        float2 acc = make_float2(0.f, 0.f);
        for (int k0 = 0; k0 < n; k0 += 32) {
            int kk = k0 + lane;
            int p = (kk < n) ? __ldg(&g_icol[start + kk]) : 0;
            int m = min(32, n - k0);
            for (int j = 0; j < m; j++) {
                int pj = __shfl_sync(0xFFFFFFFFu, p, j);
                int t  = pj & 0xFFFFF;
                int r  = pj >> 20;
                float2 e = ecur[t * 32 + lane];
                float2 w = s_w[r * 32 + lane];
                acc.x = fmaf(e.x, w.x, acc.x);
                acc.y = fmaf(e.y, w.y, acc.y);
            }
        }
        float ss = acc.x * acc.x + acc.y * acc.y;
        #pragma unroll
        for (int o = 16; o; o >>= 1) ss += __shfl_xor_sync(0xFFFFFFFFu, ss, o);
        float inv = 1.f / fmaxf(sqrtf(ss), 1e-12f);
        acc.x *= inv; acc.y *= inv;
        enxt[gw * 32 + lane] = acc;
        float2 o = out_ent[gw * 32 + lane];
        o.x += acc.x; o.y += acc.y;
        out_ent[gw * 32 + lane] = o;
    } else {
        // ---- user aggregation: sum_i val * ecur[col] ----
        int u = gw - N_ENTITIES;
        float2 acc = make_float2(0.f, 0.f);
        for (int k0 = 0; k0 < n; k0 += 32) {
            int kk = k0 + lane;
            int   c = 0;
            float v = 0.f;
            if (kk < n) {
                c = __ldg(&g_icol[start + kk]);
                v = __ldg(&g_fval[start + kk - N_EDGES]);
            }
            int m = min(32, n - k0);
            for (int j = 0; j < m; j++) {
                int   cj = __shfl_sync(0xFFFFFFFFu, c, j);
                float vj = __shfl_sync(0xFFFFFFFFu, v, j);
                float2 e = ecur[cj * 32 + lane];
                acc.x = fmaf(vj, e.x, acc.x);
                acc.y = fmaf(vj, e.y, acc.y);
            }
        }
        // score = softmax(u_cur @ latent^T); mix = score @ disen
        float2 uc = ucur[u * 32 + lane];
        float d[N_FACTORS];
        #pragma unroll
        for (int f = 0; f < N_FACTORS; f++) {
            float2 lf = __ldg(&latent2[f * 32 + lane]);
            float p = uc.x * lf.x + uc.y * lf.y;
            #pragma unroll
            for (int o = 16; o; o >>= 1) p += __shfl_xor_sync(0xFFFFFFFFu, p, o);
            d[f] = p;
        }
        float mx = fmaxf(fmaxf(d[0], d[1]), fmaxf(d[2], d[3]));
        float s[N_FACTORS], sum = 0.f;
        #pragma unroll
        for (int f = 0; f < N_FACTORS; f++) { s[f] = expf(d[f] - mx); sum += s[f]; }
        float invs = 1.f / sum;
        const float2* dw = (const float2*)g_disen;
        float2 mix = make_float2(0.f, 0.f);
        #pragma unroll
        for (int f = 0; f < N_FACTORS; f++) {
            float sf = s[f] * invs;
            float2 w2 = dw[f * 32 + lane];
            mix.x = fmaf(sf, w2.x, mix.x);
            mix.y = fmaf(sf, w2.y, mix.y);
        }
        float2 un = make_float2(acc.x * (mix.x + 1.f), acc.y * (mix.y + 1.f));
        float ss = un.x * un.x + un.y * un.y;
        #pragma unroll
        for (int o = 16; o; o >>= 1) ss += __shfl_xor_sync(0xFFFFFFFFu, ss, o);
        float inv = 1.f / fmaxf(sqrtf(ss), 1e-12f);
        un.x *= inv; un.y *= inv;
        unxt[u * 32 + lane] = un;
        float2 o = out_usr[u * 32 + lane];
        o.x += un.x; o.y += un.y;
        out_usr[u * 32 + lane] = o;
    }
}

// ---------------------------------------------------------------------------
extern "C" void kernel_launch(void* const* d_in, const int* in_sizes, int n_in,
                              void* d_out, int out_size) {
    const float* user_emb   = (const float*)d_in[0];
    const float* entity_emb = (const float*)d_in[1];
    const float* latent_emb = (const float*)d_in[2];
    const float* weight     = (const float*)d_in[3];
    const float* att        = (const float*)d_in[4];
    const float* ivals      = (const float*)d_in[5];
    const int*   head       = (const int*)d_in[6];
    const int*   tail       = (const int*)d_in[7];
    const int*   etype      = (const int*)d_in[8];
    const int*   irows      = (const int*)d_in[9];
    const int*   icols      = (const int*)d_in[10];

    float* out     = (float*)d_out;
    float* out_ent = out;
    float* out_usr = out + (size_t)N_ENTITIES * CHANNEL;
    float* out_cor = out + (size_t)(N_ENTITIES + N_USERS) * CHANNEL;

    const int TPB = 256;
    int init_blocks = (EV4 + UV4 + TPB - 1) / TPB;
    int item_blocks = (NITEMS + TPB - 1) / TPB;

    k_init<<<init_blocks, TPB>>>((const float4*)entity_emb, (const float4*)user_emb,
                                 (float4*)out_ent, (float4*)out_usr);
    k_small<<<1, 256>>>(att, weight, out_cor);

    // build CSR (counting sort by destination)
    k_zero_cnt<<<(NBINS + TPB - 1) / TPB, TPB>>>();
    k_hist<<<item_blocks, TPB>>>(head, irows);
    k_scan1<<<NBLK, CHUNK>>>();
    k_scan2<<<1, 256>>>();
    k_scan3<<<NBLK, CHUNK>>>();
    k_scatter<<<item_blocks, TPB>>>(head, tail, etype, irows, icols, ivals);

    // two fused hops
    int hop_blocks = (NBINS * 32 + TPB - 1) / TPB;
    k_hop<<<hop_blocks, TPB>>>(0, weight, (const float2*)latent_emb,
                               (float2*)out_ent, (float2*)out_usr);
    k_hop<<<hop_blocks, TPB>>>(1, weight, (const float2*)latent_emb,
                               (float2*)out_ent, (float2*)out_usr);
}

// round 7
// speedup vs baseline: 2.1768x; 1.5075x over previous
#include <cuda_runtime.h>
#include <cuda_fp16.h>

#define N_USERS    50000
#define N_ENTITIES 100000
#define CHANNEL    64
#define N_FACTORS  4
#define N_RELM1    8
#define N_EDGES    1500000
#define NNZ        800000

#define NBINS   (N_ENTITIES + N_USERS)
#define NITEMS  (N_EDGES + NNZ)
#define CHUNK   1024
#define NBLK    ((NBINS + CHUNK - 1) / CHUNK)   // 147

#define EV4 (N_ENTITIES * 16)
#define UV4 (N_USERS * 16)

// fp16 ping-pong entity tables: one row = 64ch = 32 x half2 = 128B = 1 L2 line
__device__ __half2 g_eh0[N_ENTITIES * 32];
__device__ __half2 g_eh1[N_ENTITIES * 32];
// normalized user rows after hop0 (fp32; read row-wise by owner warp only)
__device__ float2  g_un[N_USERS * 32];
__device__ float   g_disen[N_FACTORS * CHANNEL];

// CSR build
__device__ int   g_cnt[NBINS];
__device__ int   g_off[NBINS];
__device__ int   g_pos[NBINS];
__device__ int   g_bsum[NBLK];
__device__ int   g_bpre[NBLK];
__device__ int   g_ecol[N_EDGES];   // tail | (rel<<20)
__device__ int2  g_uitem[NNZ];      // {col, val bits}

// ---------------------------------------------------------------------------
// init: convert entity table to fp16, seed outputs with the raw embeddings
// ---------------------------------------------------------------------------
__global__ void k_init(const float4* __restrict__ ent, const float4* __restrict__ usr,
                       float4* __restrict__ out_ent, float4* __restrict__ out_usr) {
    int i = blockIdx.x * blockDim.x + threadIdx.x;
    if (i < EV4) {
        float4 v = ent[i];
        out_ent[i] = v;
        g_eh0[i * 2 + 0] = __floats2half2_rn(v.x, v.y);
        g_eh0[i * 2 + 1] = __floats2half2_rn(v.z, v.w);
    } else {
        int j = i - EV4;
        if (j < UV4) out_usr[j] = usr[j];
    }
}

// ---------------------------------------------------------------------------
__global__ void k_zero_cnt() {
    int i = blockIdx.x * blockDim.x + threadIdx.x;
    if (i < NBINS) g_cnt[i] = 0;
}

__global__ void k_hist(const int* __restrict__ head, const int* __restrict__ irows) {
    int i = blockIdx.x * blockDim.x + threadIdx.x;
    if (i < N_EDGES) {
        atomicAdd(&g_cnt[head[i]], 1);
    } else if (i < NITEMS) {
        atomicAdd(&g_cnt[N_ENTITIES + irows[i - N_EDGES]], 1);
    }
}

__global__ void k_scan1() {
    __shared__ int s[CHUNK];
    int b = blockIdx.x, t = threadIdx.x;
    int i = b * CHUNK + t;
    s[t] = (i < NBINS) ? g_cnt[i] : 0;
    __syncthreads();
    for (int o = CHUNK >> 1; o; o >>= 1) {
        if (t < o) s[t] += s[t + o];
        __syncthreads();
    }
    if (t == 0) g_bsum[b] = s[0];
}

__global__ void k_scan2() {
    __shared__ int s[256];
    int t = threadIdx.x;
    int v = (t < NBLK) ? g_bsum[t] : 0;
    s[t] = v;
    __syncthreads();
    for (int o = 1; o < 256; o <<= 1) {
        int x = (t >= o) ? s[t - o] : 0;
        __syncthreads();
        s[t] += x;
        __syncthreads();
    }
    if (t < NBLK) g_bpre[t] = s[t] - v;
}

__global__ void k_scan3() {
    __shared__ int s[CHUNK];
    int b = blockIdx.x, t = threadIdx.x;
    int i = b * CHUNK + t;
    int v = (i < NBINS) ? g_cnt[i] : 0;
    s[t] = v;
    __syncthreads();
    for (int o = 1; o < CHUNK; o <<= 1) {
        int x = (t >= o) ? s[t - o] : 0;
        __syncthreads();
        s[t] += x;
        __syncthreads();
    }
    if (i < NBINS) {
        int off = g_bpre[b] + s[t] - v;
        g_off[i] = off;
        g_pos[i] = off;
    }
}

__global__ void k_scatter(const int* __restrict__ head, const int* __restrict__ tail,
                          const int* __restrict__ etype,
                          const int* __restrict__ irows, const int* __restrict__ icols,
                          const float* __restrict__ ivals) {
    int i = blockIdx.x * blockDim.x + threadIdx.x;
    if (i < N_EDGES) {
        int h = head[i];
        int pos = atomicAdd(&g_pos[h], 1);
        g_ecol[pos] = tail[i] | ((etype[i] - 1) << 20);
    } else if (i < NITEMS) {
        int j = i - N_EDGES;
        int r = irows[j];
        int pos = atomicAdd(&g_pos[N_ENTITIES + r], 1) - N_EDGES;
        g_uitem[pos] = make_int2(icols[j], __float_as_int(ivals[j]));
    }
}

// ---------------------------------------------------------------------------
// distance-correlation + disen_weight = softmax(att) @ W
// ---------------------------------------------------------------------------
__device__ float dcor_pair(const float* t1, const float* t2) {
    const int ch = N_RELM1;
    float a[N_RELM1][N_RELM1], b[N_RELM1][N_RELM1];
    for (int i = 0; i < ch; i++)
        for (int j = 0; j < ch; j++) {
            float v1 = t1[i] * t1[i] - 2.f * t1[i] * t1[j] + t1[j] * t1[j];
            float v2 = t2[i] * t2[i] - 2.f * t2[i] * t2[j] + t2[j] * t2[j];
            a[i][j] = sqrtf(fmaxf(v1, 0.f) + 1e-8f);
            b[i][j] = sqrtf(fmaxf(v2, 0.f) + 1e-8f);
        }
    float arm[N_RELM1], acm[N_RELM1], brm[N_RELM1], bcm[N_RELM1];
    float am = 0.f, bm = 0.f;
    for (int i = 0; i < ch; i++) { arm[i] = acm[i] = brm[i] = bcm[i] = 0.f; }
    for (int i = 0; i < ch; i++)
        for (int j = 0; j < ch; j++) {
            arm[i] += a[i][j]; acm[j] += a[i][j]; am += a[i][j];
            brm[i] += b[i][j]; bcm[j] += b[i][j]; bm += b[i][j];
        }
    float inv = 1.f / (float)ch;
    for (int i = 0; i < ch; i++) { arm[i] *= inv; acm[i] *= inv; brm[i] *= inv; bcm[i] *= inv; }
    am *= inv * inv; bm *= inv * inv;
    float sAB = 0.f, sAA = 0.f, sBB = 0.f;
    for (int i = 0; i < ch; i++)
        for (int j = 0; j < ch; j++) {
            float A = a[i][j] - acm[j] - arm[i] + am;
            float B = b[i][j] - bcm[j] - brm[i] + bm;
            sAB += A * B; sAA += A * A; sBB += B * B;
        }
    float n2 = (float)(ch * ch);
    float dAB = sqrtf(fmaxf(sAB / n2, 0.f) + 1e-8f);
    float dAA = sqrtf(fmaxf(sAA / n2, 0.f) + 1e-8f);
    float dBB = sqrtf(fmaxf(sBB / n2, 0.f) + 1e-8f);
    return dAB / sqrtf(dAA * dBB + 1e-8f);
}

__global__ void k_small(const float* __restrict__ att, const float* __restrict__ w,
                        float* __restrict__ out_cor) {
    int t = threadIdx.x;
    if (t < N_FACTORS * CHANNEL) {
        int f = t >> 6, c = t & 63;
        float row[N_RELM1];
        float mx = -1e30f;
        for (int j = 0; j < N_RELM1; j++) { row[j] = att[f * N_RELM1 + j]; mx = fmaxf(mx, row[j]); }
        float s = 0.f;
        for (int j = 0; j < N_RELM1; j++) { row[j] = expf(row[j] - mx); s += row[j]; }
        float invs = 1.f / s;
        float acc = 0.f;
        for (int j = 0; j < N_RELM1; j++) acc += row[j] * invs * w[j * CHANNEL + c];
        g_disen[t] = acc;
    }
    if (t == 0) {
        float rows[N_FACTORS][N_RELM1];
        for (int f = 0; f < N_FACTORS; f++)
            for (int j = 0; j < N_RELM1; j++) rows[f][j] = att[f * N_RELM1 + j];
        float cor = 0.f;
        for (int i = 0; i < N_FACTORS; i++)
            for (int j = i + 1; j < N_FACTORS; j++)
                cor += dcor_pair(rows[i], rows[j]);
        *out_cor = cor;
    }
}

// ---------------------------------------------------------------------------
// fused hop: warp-per-destination. fp16 gather rows (1 L2 line each),
// fp32 accumulate, warp-uniform index loads (no shfl in the hot chain).
// Buffer selection happens IN-KERNEL (device globals must not be passed
// as kernel args from host code).
// l2_normalize(agg/cnt) == l2_normalize(agg) -> degree normalization dropped.
// ---------------------------------------------------------------------------
__global__ void k_hop(int hop, const float2* __restrict__ user_emb,
                      const float* __restrict__ weight,
                      const float2* __restrict__ latent2,
                      float2* __restrict__ out_ent, float2* __restrict__ out_usr) {
    __shared__ float2 s_w[N_RELM1 * 32];

    int tid = threadIdx.x;
    for (int i = tid; i < N_RELM1 * 32; i += blockDim.x)
        s_w[i] = ((const float2*)weight)[i];
    __syncthreads();

    int gw   = (blockIdx.x * blockDim.x + tid) >> 5;
    int lane = tid & 31;
    if (gw >= NBINS) return;

    const __half2* ecur = hop ? g_eh1 : g_eh0;
    __half2*       enxt = hop ? g_eh0 : g_eh1;

    int start = g_off[gw];
    int n     = g_cnt[gw];

    if (gw < N_ENTITIES) {
        // ---- entity aggregation: sum_e ecur[tail] * weight[rel] ----
        float2 acc = make_float2(0.f, 0.f);
        #pragma unroll 4
        for (int k = 0; k < n; k++) {
            int p = __ldg(&g_ecol[start + k]);      // warp-uniform, L1-hot
            int t = p & 0xFFFFF;
            int r = p >> 20;
            float2 e = __half22float2(__ldg(&ecur[t * 32 + lane]));
            float2 w = s_w[r * 32 + lane];
            acc.x = fmaf(e.x, w.x, acc.x);
            acc.y = fmaf(e.y, w.y, acc.y);
        }
        float ss = acc.x * acc.x + acc.y * acc.y;
        #pragma unroll
        for (int o = 16; o; o >>= 1) ss += __shfl_xor_sync(0xFFFFFFFFu, ss, o);
        float inv = 1.f / fmaxf(sqrtf(ss), 1e-12f);
        acc.x *= inv; acc.y *= inv;
        enxt[gw * 32 + lane] = __floats2half2_rn(acc.x, acc.y);
        float2 o = out_ent[gw * 32 + lane];
        o.x += acc.x; o.y += acc.y;
        out_ent[gw * 32 + lane] = o;
    } else {
        // ---- user aggregation: sum_i val * ecur[col] ----
        int u = gw - N_ENTITIES;
        int ustart = start - N_EDGES;
        float2 acc = make_float2(0.f, 0.f);
        #pragma unroll 4
        for (int k = 0; k < n; k++) {
            int2 it = __ldg(&g_uitem[ustart + k]);  // warp-uniform 8B
            float v = __int_as_float(it.y);
            float2 e = __half22float2(__ldg(&ecur[it.x * 32 + lane]));
            acc.x = fmaf(v, e.x, acc.x);
            acc.y = fmaf(v, e.y, acc.y);
        }
        // score = softmax(u_cur @ latent^T); mix = score @ disen
        float2 uc = hop ? g_un[u * 32 + lane] : user_emb[u * 32 + lane];
        float d[N_FACTORS];
        #pragma unroll
        for (int f = 0; f < N_FACTORS; f++) {
            float2 lf = __ldg(&latent2[f * 32 + lane]);
            float p = uc.x * lf.x + uc.y * lf.y;
            #pragma unroll
            for (int o = 16; o; o >>= 1) p += __shfl_xor_sync(0xFFFFFFFFu, p, o);
            d[f] = p;
        }
        float mx = fmaxf(fmaxf(d[0], d[1]), fmaxf(d[2], d[3]));
        float s[N_FACTORS], sum = 0.f;
        #pragma unroll
        for (int f = 0; f < N_FACTORS; f++) { s[f] = expf(d[f] - mx); sum += s[f]; }
        float invs = 1.f / sum;
        const float2* dw = (const float2*)g_disen;
        float2 mix = make_float2(0.f, 0.f);
        #pragma unroll
        for (int f = 0; f < N_FACTORS; f++) {
            float sf = s[f] * invs;
            float2 w2 = dw[f * 32 + lane];
            mix.x = fmaf(sf, w2.x, mix.x);
            mix.y = fmaf(sf, w2.y, mix.y);
        }
        float2 un = make_float2(acc.x * (mix.x + 1.f), acc.y * (mix.y + 1.f));
        float ss = un.x * un.x + un.y * un.y;
        #pragma unroll
        for (int o = 16; o; o >>= 1) ss += __shfl_xor_sync(0xFFFFFFFFu, ss, o);
        float inv = 1.f / fmaxf(sqrtf(ss), 1e-12f);
        un.x *= inv; un.y *= inv;
        g_un[u * 32 + lane] = un;
        float2 o = out_usr[u * 32 + lane];
        o.x += un.x; o.y += un.y;
        out_usr[u * 32 + lane] = o;
    }
}

// ---------------------------------------------------------------------------
extern "C" void kernel_launch(void* const* d_in, const int* in_sizes, int n_in,
                              void* d_out, int out_size) {
    const float* user_emb   = (const float*)d_in[0];
    const float* entity_emb = (const float*)d_in[1];
    const float* latent_emb = (const float*)d_in[2];
    const float* weight     = (const float*)d_in[3];
    const float* att        = (const float*)d_in[4];
    const float* ivals      = (const float*)d_in[5];
    const int*   head       = (const int*)d_in[6];
    const int*   tail       = (const int*)d_in[7];
    const int*   etype      = (const int*)d_in[8];
    const int*   irows      = (const int*)d_in[9];
    const int*   icols      = (const int*)d_in[10];

    float* out     = (float*)d_out;
    float* out_ent = out;
    float* out_usr = out + (size_t)N_ENTITIES * CHANNEL;
    float* out_cor = out + (size_t)(N_ENTITIES + N_USERS) * CHANNEL;

    const int TPB = 256;
    int init_blocks = (EV4 + UV4 + TPB - 1) / TPB;
    int item_blocks = (NITEMS + TPB - 1) / TPB;

    k_init<<<init_blocks, TPB>>>((const float4*)entity_emb, (const float4*)user_emb,
                                 (float4*)out_ent, (float4*)out_usr);
    k_small<<<1, 256>>>(att, weight, out_cor);

    k_zero_cnt<<<(NBINS + TPB - 1) / TPB, TPB>>>();
    k_hist<<<item_blocks, TPB>>>(head, irows);
    k_scan1<<<NBLK, CHUNK>>>();
    k_scan2<<<1, 256>>>();
    k_scan3<<<NBLK, CHUNK>>>();
    k_scatter<<<item_blocks, TPB>>>(head, tail, etype, irows, icols, ivals);

    int hop_blocks = (NBINS * 32 + TPB - 1) / TPB;
    k_hop<<<hop_blocks, TPB>>>(0, (const float2*)user_emb, weight,
                               (const float2*)latent_emb,
                               (float2*)out_ent, (float2*)out_usr);
    k_hop<<<hop_blocks, TPB>>>(1, (const float2*)user_emb, weight,
                               (const float2*)latent_emb,
                               (float2*)out_ent, (float2*)out_usr);
}